// round 1
// baseline (speedup 1.0000x reference)
#include <cuda_runtime.h>

// Problem constants (shapes are fixed by the reference's setup_inputs).
#define N_NODES 13
#define N_REAL  12
#define BB      4
#define CC      3
#define HH      256
#define WW      256
#define EE      37
#define HWSZ    (HH*WW)

// Conv tile geometry: each block computes an 8-row x 256-col stripe of one (node, batch).
// SMEM input tile: 3 channels x 11 rows (8 + 3 halo) x 264 cols (256 + 3 halo + pad).
#define TLH 11
#define TLW 264
#define TILE_ELEMS (CC*TLH*TLW)

// Scratch: sigmoid(states). 13*4*3*65536 floats = ~41 MB (uninitialized device global,
// allowed by the allocation rules).
__device__ float g_act[N_NODES*BB*CC*HWSZ];

// ---------- packed f32x2 helpers (Blackwell) ----------
__device__ __forceinline__ unsigned long long pk2(float lo, float hi){
  unsigned long long d;
  asm("mov.b64 %0, {%1, %2};" : "=l"(d) : "f"(lo), "f"(hi));
  return d;
}
__device__ __forceinline__ void upk2(unsigned long long v, float& lo, float& hi){
  asm("mov.b64 {%0, %1}, %2;" : "=f"(lo), "=f"(hi) : "l"(v));
}
__device__ __forceinline__ unsigned long long ffma2(unsigned long long a,
                                                    unsigned long long b,
                                                    unsigned long long c){
  unsigned long long d;
  asm("fma.rn.f32x2 %0, %1, %2, %3;" : "=l"(d) : "l"(a), "l"(b), "l"(c));
  return d;
}

// ---------- pass 1: sigmoid ----------
__global__ void sigmoid_kernel(const float* __restrict__ x, int n4){
  int i = blockIdx.x*blockDim.x + threadIdx.x;
  if (i >= n4) return;
  float4 v = ((const float4*)x)[i];
  v.x = __fdividef(1.f, 1.f + __expf(-v.x));
  v.y = __fdividef(1.f, 1.f + __expf(-v.y));
  v.z = __fdividef(1.f, 1.f + __expf(-v.z));
  v.w = __fdividef(1.f, 1.f + __expf(-v.w));
  ((float4*)&g_act[0])[i] = v;
}

// ---------- pass 2: fused per-edge conv + segment mean ----------
// Block: 32x8 threads. Thread (tx,ty) computes out pixels y = y0+ty, x = 8*tx .. 8*tx+7
// for all 3 output channels, as 4 f32x2 accumulators per channel.
// SAME padding for K=4, stride 1: pad_lo = 1 (out[y] uses in[y-1 .. y+2]).
__global__ void __launch_bounds__(256) conv_kernel(
    const float* __restrict__ Wt,   // [E,3,3,4,4]
    const float* __restrict__ Bs,   // [E,3]
    const int*   __restrict__ esrc, // [E]
    const int*   __restrict__ edst, // [E]
    float*       __restrict__ out)  // [12,4,3,256,256]
{
  __shared__ float  tile[TILE_ELEMS];
  __shared__ float2 wsm[144];       // flat co*48 + ci*16 + ky*4 + kx, duplicated {w,w}

  const int v  = blockIdx.z;
  const int b  = blockIdx.y;
  const int y0 = blockIdx.x * 8;
  const int tx = threadIdx.x;
  const int ty = threadIdx.y;
  const int tid = ty*32 + tx;
  const int X  = tx * 8;            // output x base; smem col index base is also X
  const int yo = y0 + ty;

  unsigned long long acc[3][4];
  #pragma unroll
  for (int co=0; co<3; co++)
    #pragma unroll
    for (int p=0; p<4; p++) acc[co][p] = 0ull;
  float bs[3] = {0.f, 0.f, 0.f};
  int deg = 0;

  for (int e=0; e<EE; e++){
    if (__ldg(&edst[e]) != v) continue;   // uniform across block
    deg++;
    const int s = __ldg(&esrc[e]);
    #pragma unroll
    for (int co=0; co<3; co++) bs[co] += __ldg(&Bs[e*3 + co]);

    __syncthreads();                      // protect prior iter's tile/wsm reads
    if (tid < 144){
      float w = __ldg(&Wt[e*144 + tid]);
      wsm[tid] = make_float2(w, w);
    }
    // Cooperative fill of padded input tile (zero padding at borders).
    const float* base = g_act + ((size_t)s*BB + b)*CC*HWSZ;
    for (int idx = tid; idx < TILE_ELEMS; idx += 256){
      int ci  = idx / (TLH*TLW);
      int rem = idx - ci*(TLH*TLW);
      int r   = rem / TLW;
      int c   = rem - r*TLW;
      int gx  = c - 1;
      int gy  = y0 + r - 1;
      float val = 0.f;
      if ((unsigned)gx < (unsigned)WW && (unsigned)gy < (unsigned)HH)
        val = __ldg(base + ci*HWSZ + gy*WW + gx);
      tile[idx] = val;
    }
    __syncthreads();

    #pragma unroll
    for (int ci=0; ci<3; ci++){
      #pragma unroll
      for (int ky=0; ky<4; ky++){
        // smem row for input y = yo + ky - 1  -> row index ty+ky (row 0 = y0-1)
        const float* row = &tile[ci*(TLH*TLW) + (ty+ky)*TLW + X];
        float4 a0 = *(const float4*)(row);      // 16B aligned: X % 8 == 0
        float4 a1 = *(const float4*)(row + 4);
        float4 a2 = *(const float4*)(row + 8);
        float f[12] = {a0.x,a0.y,a0.z,a0.w, a1.x,a1.y,a1.z,a1.w, a2.x,a2.y,a2.z,a2.w};
        unsigned long long pr[10];
        #pragma unroll
        for (int j=0; j<10; j++) pr[j] = pk2(f[j], f[j+1]);   // {in[j], in[j+1]}

        #pragma unroll
        for (int co=0; co<3; co++){
          const unsigned long long* wp =
              (const unsigned long long*)&wsm[(co*3 + ci)*16 + ky*4];
          unsigned long long w0 = wp[0], w1 = wp[1], w2 = wp[2], w3 = wp[3];
          #pragma unroll
          for (int p=0; p<4; p++){
            acc[co][p] = ffma2(pr[2*p + 0], w0, acc[co][p]);
            acc[co][p] = ffma2(pr[2*p + 1], w1, acc[co][p]);
            acc[co][p] = ffma2(pr[2*p + 2], w2, acc[co][p]);
            acc[co][p] = ffma2(pr[2*p + 3], w3, acc[co][p]);
          }
        }
      }
    }
  }

  const float inv = 1.f / (float)deg;
  float* obase = out + (((size_t)v*BB + b)*CC)*HWSZ + yo*WW + X;
  #pragma unroll
  for (int co=0; co<3; co++){
    float r[8];
    #pragma unroll
    for (int p=0; p<4; p++){
      float lo, hi;
      upk2(acc[co][p], lo, hi);
      r[2*p]   = (lo + bs[co]) * inv;
      r[2*p+1] = (hi + bs[co]) * inv;
    }
    float4* o = (float4*)(obase + co*HWSZ);
    o[0] = make_float4(r[0], r[1], r[2], r[3]);
    o[1] = make_float4(r[4], r[5], r[6], r[7]);
  }
}

extern "C" void kernel_launch(void* const* d_in, const int* in_sizes, int n_in,
                              void* d_out, int out_size){
  const float* states  = (const float*)d_in[0];
  const float* weights = (const float*)d_in[1];
  const float* bias    = (const float*)d_in[2];
  const int*   esrc    = (const int*)d_in[3];
  const int*   edst    = (const int*)d_in[4];
  float*       out     = (float*)d_out;

  const int n4 = (N_NODES*BB*CC*HWSZ) / 4;        // 2,555,904
  sigmoid_kernel<<<(n4 + 255)/256, 256>>>(states, n4);

  dim3 grid(HH/8, BB, N_REAL);                    // (32, 4, 12) = 1536 blocks
  dim3 block(32, 8);
  conv_kernel<<<grid, block>>>(weights, bias, esrc, edst, out);
}

// round 3
// speedup vs baseline: 1.2696x; 1.2696x over previous
#include <cuda_runtime.h>

#define N_NODES 13
#define N_REAL  12
#define BB      4
#define CC      3
#define HH      256
#define WW      256
#define EE      37
#define HWSZ    (HH*WW)

// Packed tile: pair j = {in[x=j], in[x=j+128]}, j from -1..129 stored at jj=j+1 (0..130).
#define PROW 132                    // float2 per row (131 used, pad to 132)
#define TROWS 11                    // 8 out rows + 3 halo
typedef unsigned long long ull;

__device__ float g_act[N_NODES*BB*CC*HWSZ];

__device__ __forceinline__ void upk2(ull v, float& lo, float& hi){
  asm("mov.b64 {%0, %1}, %2;" : "=f"(lo), "=f"(hi) : "l"(v));
}
__device__ __forceinline__ ull ffma2(ull a, ull b, ull c){
  ull d;
  asm("fma.rn.f32x2 %0, %1, %2, %3;" : "=l"(d) : "l"(a), "l"(b), "l"(c));
  return d;
}

// ---------- pass 1: sigmoid ----------
__global__ void sigmoid_kernel(const float* __restrict__ x, int n4){
  int i = blockIdx.x*blockDim.x + threadIdx.x;
  if (i >= n4) return;
  float4 v = ((const float4*)x)[i];
  v.x = __fdividef(1.f, 1.f + __expf(-v.x));
  v.y = __fdividef(1.f, 1.f + __expf(-v.y));
  v.z = __fdividef(1.f, 1.f + __expf(-v.z));
  v.w = __fdividef(1.f, 1.f + __expf(-v.w));
  ((float4*)&g_act[0])[i] = v;
}

// ---------- pass 2: fused conv + segment mean ----------
// Block (32,4): thread (tx,ty) computes output pair-cols pc = tx+32m (m=0..3),
// i.e. columns {pc, pc+128}, for 2 rows (2*ty, 2*ty+1). Block = 8 rows x 256 cols.
__global__ void __launch_bounds__(128, 3) conv_kernel(
    const float* __restrict__ Wt,   // [E,3,3,4,4]
    const float* __restrict__ Bs,   // [E,3]
    const int*   __restrict__ esrc,
    const int*   __restrict__ edst,
    float*       __restrict__ out)  // [12,4,3,256,256]
{
  __shared__ float2 pk[CC*TROWS*PROW];   // packed input tile, ~34.8 KB
  __shared__ float2 wsm[144];            // weights duplicated {w,w}

  const int v   = blockIdx.z;
  const int b   = blockIdx.y;
  const int y0  = blockIdx.x * 8;
  const int tx  = threadIdx.x;
  const int ty  = threadIdx.y;
  const int tid = ty*32 + tx;
  const int r0  = 2*ty;                  // local out rows r0, r0+1

  ull acc[3][2][4];
  #pragma unroll
  for (int co=0; co<3; co++)
    #pragma unroll
    for (int rl=0; rl<2; rl++)
      #pragma unroll
      for (int m=0; m<4; m++) acc[co][rl][m] = 0ull;
  float bs[3] = {0.f,0.f,0.f};
  int deg = 0;

  for (int e=0; e<EE; e++){
    if (__ldg(&edst[e]) != v) continue;      // uniform across block
    deg++;
    const int s = __ldg(&esrc[e]);
    #pragma unroll
    for (int co=0; co<3; co++) bs[co] += __ldg(&Bs[e*3+co]);

    __syncthreads();                          // protect prior iter's reads
    for (int i = tid; i < 144; i += 128){
      float w = __ldg(&Wt[e*144 + i]);
      wsm[i] = make_float2(w, w);
    }
    // Structured fill: one warp per (ci,row) task, 33 tasks, 4 warps.
    const float* base = g_act + ((size_t)s*BB + b)*CC*HWSZ;
    for (int t = ty; t < CC*TROWS; t += 4){
      int ci = t / TROWS;
      int r  = t - ci*TROWS;
      int gy = y0 + r - 1;
      float2* dst = &pk[t*PROW];
      if ((unsigned)gy < (unsigned)HH){
        const float* rowp = base + ci*HWSZ + gy*WW;
        #pragma unroll
        for (int m=0; m<4; m++){
          int x = tx + 32*m;                  // 0..127
          dst[x+1] = make_float2(__ldg(rowp + x), __ldg(rowp + x + 128));
        }
        if (tx == 0) dst[0]   = make_float2(0.f, __ldg(rowp+127));
        if (tx == 1) dst[129] = make_float2(__ldg(rowp+128), 0.f);
        if (tx == 2) dst[130] = make_float2(__ldg(rowp+129), 0.f);
      } else {
        #pragma unroll
        for (int m=0; m<4; m++) dst[tx + 32*m + 1] = make_float2(0.f,0.f);
        if (tx == 0) dst[0]   = make_float2(0.f,0.f);
        if (tx == 1) dst[129] = make_float2(0.f,0.f);
        if (tx == 2) dst[130] = make_float2(0.f,0.f);
      }
    }
    __syncthreads();

    // Compute. Input pair for (pc, kx): jj = pc + kx = tx + 32m + kx. All aligned LDS.64.
    #pragma unroll
    for (int ci=0; ci<3; ci++){
      const ull* rb = (const ull*)(pk + ci*TROWS*PROW) + tx;
      ull A[4][4], B[4][4];
      {
        const ull* rp = rb + (size_t)r0*PROW;
        #pragma unroll
        for (int m=0; m<4; m++)
          #pragma unroll
          for (int k=0; k<4; k++) A[m][k] = rp[32*m + k];
      }
      #pragma unroll
      for (int ky=0; ky<4; ky++){
        const ull* rp = rb + (size_t)(r0+ky+1)*PROW;
        #pragma unroll
        for (int m=0; m<4; m++)
          #pragma unroll
          for (int k=0; k<4; k++) B[m][k] = rp[32*m + k];

        #pragma unroll
        for (int co=0; co<3; co++){
          const ull* wp = (const ull*)(wsm + (co*3+ci)*16 + ky*4);
          #pragma unroll
          for (int kx=0; kx<4; kx++){
            ull w = wp[kx];                   // broadcast LDS.64
            #pragma unroll
            for (int m=0; m<4; m++){
              acc[co][0][m] = ffma2(A[m][kx], w, acc[co][0][m]);
              acc[co][1][m] = ffma2(B[m][kx], w, acc[co][1][m]);
            }
          }
        }
        if (ky < 3){
          #pragma unroll
          for (int m=0; m<4; m++)
            #pragma unroll
            for (int k=0; k<4; k++) A[m][k] = B[m][k];   // renamed away (full unroll)
        }
      }
    }
  }

  const float inv = 1.f / (float)deg;
  #pragma unroll
  for (int co=0; co<3; co++){
    #pragma unroll
    for (int rl=0; rl<2; rl++){
      float* ob = out + (((size_t)v*BB + b)*CC + co)*HWSZ + (y0 + r0 + rl)*WW;
      #pragma unroll
      for (int m=0; m<4; m++){
        float lo, hi;
        upk2(acc[co][rl][m], lo, hi);
        int x = tx + 32*m;
        ob[x]       = (lo + bs[co]) * inv;
        ob[x + 128] = (hi + bs[co]) * inv;
      }
    }
  }
}

extern "C" void kernel_launch(void* const* d_in, const int* in_sizes, int n_in,
                              void* d_out, int out_size){
  const float* states  = (const float*)d_in[0];
  const float* weights = (const float*)d_in[1];
  const float* bias    = (const float*)d_in[2];
  const int*   esrc    = (const int*)d_in[3];
  const int*   edst    = (const int*)d_in[4];
  float*       out     = (float*)d_out;

  const int n4 = (N_NODES*BB*CC*HWSZ) / 4;
  sigmoid_kernel<<<(n4 + 255)/256, 256>>>(states, n4);

  dim3 grid(HH/8, BB, N_REAL);       // (32,4,12)
  dim3 block(32, 4);
  conv_kernel<<<grid, block>>>(weights, bias, esrc, edst, out);
}

// round 4
// speedup vs baseline: 1.4043x; 1.1061x over previous
#include <cuda_runtime.h>
#include <cstdint>

#define N_NODES 13
#define N_REAL  12
#define BB      4
#define CC      3
#define HH      256
#define WW      256
#define EE      37
#define HWSZ    (HH*WW)

// Tile: 3 ci x 11 rows x 130 float2. Row layout: idx 0..127 = pairs {2j,2j+1}
// (contiguous gmem, cp.async-able), idx 128 = pair j=128 (zeros), idx 129 = pair
// j=-1 (zeros). Row = 130*8 = 1040 B (16B-aligned rows).
#define TROWS 11
#define PROW  130
#define TILE_F2 (CC*TROWS*PROW)      // 4290 float2
#define TILE_BYTES (TILE_F2*8)       // 34320
typedef unsigned long long ull;

__device__ float g_act[N_NODES*BB*CC*HWSZ];

__device__ __forceinline__ ull pk2(float lo, float hi){
  ull d; asm("mov.b64 %0, {%1, %2};" : "=l"(d) : "f"(lo), "f"(hi)); return d;
}
__device__ __forceinline__ void upk2(ull v, float& lo, float& hi){
  asm("mov.b64 {%0, %1}, %2;" : "=f"(lo), "=f"(hi) : "l"(v));
}
__device__ __forceinline__ ull ffma2(ull a, ull b, ull c){
  ull d; asm("fma.rn.f32x2 %0, %1, %2, %3;" : "=l"(d) : "l"(a), "l"(b), "l"(c));
  return d;
}
__device__ __forceinline__ void cp16(uint32_t s, const void* g){
  asm volatile("cp.async.cg.shared.global [%0], [%1], 16;" :: "r"(s), "l"(g));
}

// ---------- pass 1: sigmoid ----------
__global__ void sigmoid_kernel(const float* __restrict__ x, int n4){
  int i = blockIdx.x*blockDim.x + threadIdx.x;
  if (i >= n4) return;
  float4 v = ((const float4*)x)[i];
  v.x = __fdividef(1.f, 1.f + __expf(-v.x));
  v.y = __fdividef(1.f, 1.f + __expf(-v.y));
  v.z = __fdividef(1.f, 1.f + __expf(-v.z));
  v.w = __fdividef(1.f, 1.f + __expf(-v.w));
  ((float4*)&g_act[0])[i] = v;
}

// ---------- pass 2: fused conv + segment mean, cp.async double-buffered ----------
// Block (32,4). Thread (tx,ty): out rows 2ty,2ty+1; out col pairs q=tx+32m (m=0..3)
// covering columns {2q, 2q+1}.
extern __shared__ float2 dynsmem[];

__global__ void __launch_bounds__(128, 3) conv_kernel(
    const float* __restrict__ Wt,   // [E,3,3,4,4]
    const float* __restrict__ Bs,   // [E,3]
    const int*   __restrict__ esrc,
    const int*   __restrict__ edst,
    float*       __restrict__ out)  // [12,4,3,256,256]
{
  __shared__ float2 w_all[4*144];   // duplicated {w,w} for up to 4 edges
  __shared__ int s_eidx[4], s_src[4], s_deg;

  const int v   = blockIdx.z;
  const int b   = blockIdx.y;
  const int y0  = blockIdx.x * 8;
  const int tx  = threadIdx.x;
  const int ty  = threadIdx.y;
  const int tid = ty*32 + tx;
  const int r0  = 2*ty;

  float2* buf[2] = { dynsmem, dynsmem + TILE_F2 };
  const uint32_t dyn_u32 = (uint32_t)__cvta_generic_to_shared(dynsmem);

  // ---- one-time init: zero halo pairs + out-of-range rows (both buffers) ----
  const float2 z2 = make_float2(0.f, 0.f);
  for (int bi=0; bi<2; bi++){
    float2* T = buf[bi];
    for (int t=tid; t<CC*TROWS; t+=128){ T[t*PROW+128]=z2; T[t*PROW+129]=z2; }
    #pragma unroll
    for (int r=0; r<TROWS; r++){
      int gy = y0 + r - 1;
      if ((unsigned)gy >= (unsigned)HH){
        for (int ci=0; ci<CC; ci++)
          for (int i=tid; i<128; i+=128) {  // each thread writes distinct idx
            T[(ci*TROWS+r)*PROW + i] = z2;
          }
      }
    }
  }

  // ---- edge scan + weight/bias preload ----
  if (tid == 0){
    int d = 0;
    for (int e=0; e<EE; e++)
      if (__ldg(&edst[e]) == v){ s_eidx[d]=e; s_src[d]=__ldg(&esrc[e]); d++; }
    s_deg = d;
  }
  __syncthreads();
  const int deg = s_deg;
  for (int i=0; i<deg; i++)
    for (int j=tid; j<144; j+=128){
      float w = __ldg(&Wt[s_eidx[i]*144 + j]);
      w_all[i*144 + j] = make_float2(w, w);
    }
  float bsum[3] = {0.f,0.f,0.f};
  for (int i=0; i<deg; i++)
    #pragma unroll
    for (int co=0; co<3; co++) bsum[co] += __ldg(&Bs[s_eidx[i]*3+co]);

  // per-m pair indices (float2 index within a row)
  int im1[4], i0[4], ip1[4];
  #pragma unroll
  for (int m=0; m<4; m++){
    int q = tx + 32*m;
    i0[m]  = q;
    ip1[m] = q + 1;              // q=127 -> 128 (zero pair)
    im1[m] = (q == 0) ? 129 : q - 1;
  }

  ull accA[3][4], accB[3][4];
  #pragma unroll
  for (int co=0; co<3; co++)
    #pragma unroll
    for (int m=0; m<4; m++){ accA[co][m]=0ull; accB[co][m]=0ull; }

  // ---- async fill of a buffer for edge slot ----
  auto fill_async = [&](int bi, int src_node){
    const float* base = g_act + ((size_t)src_node*BB + b)*CC*HWSZ;
    uint32_t t_u32 = dyn_u32 + (uint32_t)(bi*TILE_BYTES);
    for (int t=ty; t<CC*TROWS; t+=4){
      int ci = t / TROWS;
      int r  = t - ci*TROWS;
      int gy = y0 + r - 1;
      if ((unsigned)gy < (unsigned)HH){
        const float* gp = base + ci*HWSZ + gy*WW + tx*4;
        uint32_t sd = t_u32 + (uint32_t)(t*PROW*8) + (uint32_t)(tx*16);
        cp16(sd,       gp);
        cp16(sd + 512, gp + 128);
      }
    }
  };

  __syncthreads();                      // zero-init visible to all
  fill_async(0, s_src[0]);
  asm volatile("cp.async.commit_group;" ::: "memory");
  asm volatile("cp.async.wait_group 0;" ::: "memory");
  __syncthreads();

  for (int i=0; i<deg; i++){
    const float2* cur = buf[i & 1];
    if (i+1 < deg) fill_async((i+1) & 1, s_src[i+1]);
    asm volatile("cp.async.commit_group;" ::: "memory");

    const float2* wbase = w_all + i*144;
    #pragma unroll
    for (int ci=0; ci<3; ci++){
      const float2* tb = cur + ci*(TROWS*PROW);
      float2 a[4][3], bb[4][3];
      {
        const float2* rp = tb + r0*PROW;
        #pragma unroll
        for (int m=0; m<4; m++){ a[m][0]=rp[im1[m]]; a[m][1]=rp[i0[m]]; a[m][2]=rp[ip1[m]]; }
      }
      #pragma unroll
      for (int ky=0; ky<4; ky++){
        const float2* rq = tb + (r0+ky+1)*PROW;
        #pragma unroll
        for (int m=0; m<4; m++){ bb[m][0]=rq[im1[m]]; bb[m][1]=rq[i0[m]]; bb[m][2]=rq[ip1[m]]; }

        ull w[3][4];
        #pragma unroll
        for (int co=0; co<3; co++){
          const ull* wp = (const ull*)(wbase + (co*3+ci)*16 + ky*4);
          #pragma unroll
          for (int kx=0; kx<4; kx++) w[co][kx] = wp[kx];   // broadcast LDS.64
        }

        #pragma unroll
        for (int m=0; m<4; m++){
          // taps for out pair {2q,2q+1}: kx0={2q-1,2q} kx1={2q,2q+1} kx2={2q+1,2q+2} kx3={2q+2,2q+3}
          ull a0 = pk2(a[m][0].y,  a[m][1].x);
          ull a1 = pk2(a[m][1].x,  a[m][1].y);
          ull a2 = pk2(a[m][1].y,  a[m][2].x);
          ull a3 = pk2(a[m][2].x,  a[m][2].y);
          ull b0 = pk2(bb[m][0].y, bb[m][1].x);
          ull b1 = pk2(bb[m][1].x, bb[m][1].y);
          ull b2 = pk2(bb[m][1].y, bb[m][2].x);
          ull b3 = pk2(bb[m][2].x, bb[m][2].y);
          #pragma unroll
          for (int co=0; co<3; co++){
            accA[co][m] = ffma2(a0, w[co][0], accA[co][m]);
            accA[co][m] = ffma2(a1, w[co][1], accA[co][m]);
            accA[co][m] = ffma2(a2, w[co][2], accA[co][m]);
            accA[co][m] = ffma2(a3, w[co][3], accA[co][m]);
            accB[co][m] = ffma2(b0, w[co][0], accB[co][m]);
            accB[co][m] = ffma2(b1, w[co][1], accB[co][m]);
            accB[co][m] = ffma2(b2, w[co][2], accB[co][m]);
            accB[co][m] = ffma2(b3, w[co][3], accB[co][m]);
          }
        }
        if (ky < 3){
          #pragma unroll
          for (int m=0; m<4; m++){ a[m][0]=bb[m][0]; a[m][1]=bb[m][1]; a[m][2]=bb[m][2]; }
        }
      }
    }

    asm volatile("cp.async.wait_group 0;" ::: "memory");
    __syncthreads();
  }

  // ---- epilogue: bias + mean, store ----
  const float inv = 1.f / (float)deg;
  #pragma unroll
  for (int co=0; co<3; co++){
    float* ob0 = out + (((size_t)v*BB + b)*CC + co)*HWSZ + (y0 + r0)*WW;
    float* ob1 = ob0 + WW;
    #pragma unroll
    for (int m=0; m<4; m++){
      int col = 2*(tx + 32*m);
      float lo, hi;
      upk2(accA[co][m], lo, hi);
      *(float2*)(ob0 + col) = make_float2((lo + bsum[co])*inv, (hi + bsum[co])*inv);
      upk2(accB[co][m], lo, hi);
      *(float2*)(ob1 + col) = make_float2((lo + bsum[co])*inv, (hi + bsum[co])*inv);
    }
  }
}

extern "C" void kernel_launch(void* const* d_in, const int* in_sizes, int n_in,
                              void* d_out, int out_size){
  const float* states  = (const float*)d_in[0];
  const float* weights = (const float*)d_in[1];
  const float* bias    = (const float*)d_in[2];
  const int*   esrc    = (const int*)d_in[3];
  const int*   edst    = (const int*)d_in[4];
  float*       out     = (float*)d_out;

  const int n4 = (N_NODES*BB*CC*HWSZ) / 4;
  sigmoid_kernel<<<(n4 + 255)/256, 256>>>(states, n4);

  static int smem_set = 0;
  if (!smem_set){
    cudaFuncSetAttribute(conv_kernel, cudaFuncAttributeMaxDynamicSharedMemorySize,
                         2*TILE_BYTES);
    smem_set = 1;
  }
  dim3 grid(HH/8, BB, N_REAL);       // (32,4,12)
  dim3 block(32, 4);
  conv_kernel<<<grid, block, 2*TILE_BYTES>>>(weights, bias, esrc, edst, out);
}